// round 7
// baseline (speedup 1.0000x reference)
#include <cuda_runtime.h>
#include <cuda_fp16.h>
#include <cstdint>

// Problem constants (fixed by the dataset)
#define PM 4
#define PK 8192
#define PKK (PK/2)            // 4096 packed-k rows
#define PN 28672
#define PG 128                // group size (k elements)
// Geometry
#define THREADS 256
#define COLS_PER_THREAD 4
#define COLS_PER_CTA (THREADS*COLS_PER_THREAD)   // 1024
#define NB (PN/COLS_PER_CTA)                     // 28
#define KSPLIT 32
#define KK_PER_SPLIT (PKK/KSPLIT)                // 128
#define GROUPS_PER_SPLIT (KK_PER_SPLIT/(PG/2))   // 2
#define BATCH 4
#define NBATCH (KK_PER_SPLIT/BATCH)              // 32
#define BATCHES_PER_GROUP ((PG/2)/BATCH)         // 16

// Split-K partials: [KSPLIT][M][N] fp32 (fits in L2: 14.7MB). Static device global.
__device__ float g_scratch[KSPLIT * PM * PN];
// Per-column-strip completion counters (zero-init; reducer resets -> graph-safe).
__device__ unsigned int g_cnt[NB];

// Packed f32x2 FMA (Blackwell, PTX-only)
__device__ __forceinline__ void fma_f32x2(unsigned long long& acc,
                                          unsigned long long a,
                                          unsigned long long b) {
    asm("fma.rn.f32x2 %0, %1, %2, %0;" : "+l"(acc) : "l"(a), "l"(b));
}
__device__ __forceinline__ unsigned long long pack_f32x2(float lo, float hi) {
    unsigned long long r;
    asm("mov.b64 %0, {%1, %2};" : "=l"(r) : "f"(lo), "f"(hi));
    return r;
}
__device__ __forceinline__ void unpack_f32x2(unsigned long long v, float& lo, float& hi) {
    asm("mov.b64 {%0, %1}, %2;" : "=f"(lo), "=f"(hi) : "l"(v));
}

__global__ void __launch_bounds__(THREADS, 2)
int4gemv_fused(const float* __restrict__ x,      // fp16 promoted to f32 by harness
               const int*   __restrict__ w,
               const float* __restrict__ scales, // fp16 promoted to f32 by harness
               const float* __restrict__ bias,   // fp16 promoted to f32 by harness
               float*       __restrict__ out)
{
    // Per kk: 4 packed (x_even, x_odd) f32 pairs, one per m-row.
    __shared__ unsigned long long xs2[KK_PER_SPLIT * 4];   // 4KB
    __shared__ int s_is_last;

    const int tid     = threadIdx.x;
    const int nb      = blockIdx.x;
    const int ks      = blockIdx.y;
    const int kk0     = ks * KK_PER_SPLIT;
    const int colBase = nb * COLS_PER_CTA + tid * COLS_PER_THREAD;

    // Preload x slice: xs2[kk*4 + m] = (x[m][2kk], x[m][2kk+1])
    {
        float* xsf = reinterpret_cast<float*>(xs2);
        for (int i = tid; i < KK_PER_SPLIT * 8; i += THREADS) {
            int kkl = i >> 3;
            int r   = i & 7;
            int m   = r >> 1;
            int j   = r & 1;
            xsf[(kkl * 4 + m) * 2 + j] = x[m * PK + 2 * (kk0 + kkl) + j];
        }
    }
    __syncthreads();

    // acc2[c][m] = (sum over even k, sum over odd k) as packed f32x2
    unsigned long long acc2[COLS_PER_THREAD][PM];
    #pragma unroll
    for (int c = 0; c < COLS_PER_THREAD; ++c)
        #pragma unroll
        for (int m = 0; m < PM; ++m) acc2[c][m] = 0ull;

    const int* wp = w + (size_t)kk0 * PN + colBase;
    const __half2 c1032 = __half2half2(__ushort_as_half((unsigned short)0x6408)); // 1032.0h

    // Software-pipelined: double-buffered batches of 4 int4 loads.
    int4 buf[2][BATCH];

    // Prologue: load batch 0.
    #pragma unroll
    for (int j = 0; j < BATCH; ++j)
        buf[0][j] = *reinterpret_cast<const int4*>(wp + j * PN);
    wp += BATCH * PN;

    // Prefetch one batch past split end is safe except for the very last split.
    const bool tail_ok = (ks != KSPLIT - 1);

    __half2 s2[COLS_PER_THREAD];
    #pragma unroll
    for (int b = 0; b < NBATCH; ++b) {
        const int pb  = b & 1;
        const int nb2 = pb ^ 1;

        // Refresh scales at group boundaries (compile-time condition after unroll).
        if ((b & (BATCHES_PER_GROUP - 1)) == 0) {
            const int grow = ks * GROUPS_PER_SPLIT + (b / BATCHES_PER_GROUP);
            float4 sv = *reinterpret_cast<const float4*>(scales + (size_t)grow * PN + colBase);
            s2[0] = __half2half2(__float2half_rn(sv.x));
            s2[1] = __half2half2(__float2half_rn(sv.y));
            s2[2] = __half2half2(__float2half_rn(sv.z));
            s2[3] = __half2half2(__float2half_rn(sv.w));
        }

        // Prefetch next batch while computing this one.
        if (b + 1 < NBATCH) {
            #pragma unroll
            for (int j = 0; j < BATCH; ++j)
                buf[nb2][j] = *reinterpret_cast<const int4*>(wp + j * PN);
            wp += BATCH * PN;
        } else if (tail_ok) {
            #pragma unroll
            for (int j = 0; j < BATCH; ++j)
                buf[nb2][j] = *reinterpret_cast<const int4*>(wp + j * PN);
        }

        // Compute batch b: 4 consecutive kk rows.
        #pragma unroll
        for (int j = 0; j < BATCH; ++j) {
            const int kkl = b * BATCH + j;
            const unsigned long long* xp = &xs2[kkl * 4];
            unsigned long long xm0 = xp[0];
            unsigned long long xm1 = xp[1];
            unsigned long long xm2 = xp[2];
            unsigned long long xm3 = xp[3];

            int4 wv = buf[pb][j];
            int wb[4] = {wv.x, wv.y, wv.z, wv.w};
            #pragma unroll
            for (int c = 0; c < 4; ++c) {
                // nibble -> fp16 magic: (0x6400 | nib) = 1024 + nib ; exact -1032 => nib-8
                unsigned int bb = (unsigned int)wb[c];
                unsigned int t = (((bb << 12) | bb) & 0x000F000Fu) | 0x64006400u;
                __half2 h2 = *reinterpret_cast<__half2*>(&t);
                __half2 w2 = __hsub2(h2, c1032);     // exact: (w-8) in fp16
                __half2 dq = __hmul2(w2, s2[c]);     // fp16 round == reference deq
                float d0 = __half2float(__low2half(dq));   // even k
                float d1 = __half2float(__high2half(dq));  // odd  k
                unsigned long long d64 = pack_f32x2(d0, d1);

                fma_f32x2(acc2[c][0], xm0, d64);
                fma_f32x2(acc2[c][1], xm1, d64);
                fma_f32x2(acc2[c][2], xm2, d64);
                fma_f32x2(acc2[c][3], xm3, d64);
            }
        }
    }

    // Collapse even/odd halves and write split partials (coalesced float4 per row).
    float* sc = g_scratch + (size_t)ks * PM * PN;
    #pragma unroll
    for (int m = 0; m < PM; ++m) {
        float r[4];
        #pragma unroll
        for (int c = 0; c < 4; ++c) {
            float lo, hi;
            unpack_f32x2(acc2[c][m], lo, hi);
            r[c] = lo + hi;
        }
        float4 v = make_float4(r[0], r[1], r[2], r[3]);
        *reinterpret_cast<float4*>(sc + m * PN + colBase) = v;
    }

    // ---- Fused reduction: last CTA of this column strip sums all partials ----
    if (tid == 0) {
        __threadfence();   // release our partial writes
        unsigned int old = atomicAdd(&g_cnt[nb], 1u);
        s_is_last = (old == KSPLIT - 1);
    }
    __syncthreads();
    if (!s_is_last) return;

    __threadfence();       // acquire all strips' partial writes
    if (tid == 0) g_cnt[nb] = 0;   // reset for next graph replay (deterministic)

    // Each thread reduces its 4 columns for all 4 m-rows. Scratch is L2-hot.
    #pragma unroll
    for (int m = 0; m < PM; ++m) {
        float4 s = make_float4(0.f, 0.f, 0.f, 0.f);
        #pragma unroll
        for (int k2 = 0; k2 < KSPLIT; ++k2) {
            const float4 p = *reinterpret_cast<const float4*>(
                &g_scratch[(size_t)k2 * PM * PN + m * PN + colBase]);
            s.x += p.x; s.y += p.y; s.z += p.z; s.w += p.w;
        }
        float4 bv = *reinterpret_cast<const float4*>(&bias[colBase]);
        float4 o;
        // Match reference exactly: f32 -> fp16 round, fp16 bias add, back to f32.
        o.x = __half2float(__hadd(__float2half_rn(s.x), __float2half_rn(bv.x)));
        o.y = __half2float(__hadd(__float2half_rn(s.y), __float2half_rn(bv.y)));
        o.z = __half2float(__hadd(__float2half_rn(s.z), __float2half_rn(bv.z)));
        o.w = __half2float(__hadd(__float2half_rn(s.w), __float2half_rn(bv.w)));
        *reinterpret_cast<float4*>(&out[m * PN + colBase]) = o;
    }
}

extern "C" void kernel_launch(void* const* d_in, const int* in_sizes, int n_in,
                              void* d_out, int out_size)
{
    // Bind inputs BY ELEMENT COUNT (dtype-invariant, robust to ordering):
    //   x: 32768, weight_packed: 117440512, scales: 6422528, bias: 28672
    const float* x      = nullptr;
    const int*   w      = nullptr;
    const float* scales = nullptr;
    const float* bias   = nullptr;

    for (int i = 0; i < n_in; ++i) {
        switch (in_sizes[i]) {
            case PM * PK:        x      = (const float*)d_in[i]; break;
            case PKK * PN:       w      = (const int*)  d_in[i]; break;
            case (PK/PG) * PN:   scales = (const float*)d_in[i]; break;
            case PN:             bias   = (const float*)d_in[i]; break;
            default: break; // group_size scalar etc.
        }
    }

    float* out = (float*)d_out;

    dim3 grid(NB, KSPLIT);
    int4gemv_fused<<<grid, THREADS>>>(x, w, scales, bias, out);
}